// round 3
// baseline (speedup 1.0000x reference)
#include <cuda_runtime.h>
#include <cstdint>

// Problem constants (fixed shapes from reference)
#define SS 256        // S
#define WW 64         // W
#define MM 64         // M
#define BB 32         // B
#define WM 4096       // W*M
#define ELEMS 33554432  // B*S*W*M
#define TC 32         // columns (m) per CTA tile

// Device-global scratch (allowed; no runtime allocation)
__device__ int                d_row_ptr[SS + 1];
__device__ unsigned long long d_csr[SS * SS];      // packed (weight<<32 | j)
__device__ float2             d_tbl[SS * WW];      // (decay*cos, decay*sin) per (s,w)
__device__ float2             d_scratch[ELEMS];    // 268MB interleaved field buffer

// ---------------------------------------------------------------------------
// Prep: build CSR of connectivity + fused phase/decay table. 1 CTA, 256 thr.
// Deterministic, runs every launch (~microseconds).
// ---------------------------------------------------------------------------
__global__ void prep_kernel(const float* __restrict__ conn,
                            const float* __restrict__ ww,
                            const float* __restrict__ disp) {
    __shared__ int cnt[SS + 1];
    int t = threadIdx.x;

    int c = 0;
    for (int j = 0; j < SS; j++)
        if (conn[t * SS + j] != 0.0f) c++;
    cnt[t + 1] = c;
    if (t == 0) cnt[0] = 0;
    __syncthreads();
    if (t == 0) {
        for (int i = 1; i <= SS; i++) cnt[i] += cnt[i - 1];
    }
    __syncthreads();

    int p = cnt[t];
    for (int j = 0; j < SS; j++) {
        float v = conn[t * SS + j];
        if (v != 0.0f) {
            d_csr[p++] = ((unsigned long long)__float_as_uint(v) << 32) | (unsigned)j;
        }
    }
    d_row_ptr[t] = cnt[t];
    if (t == SS - 1) d_row_ptr[SS] = cnt[SS];

    // fused phase * decay table: phase = exp(i*0.1*disp[w]), decay = 0.95*ww[s][w]
    for (int i = t; i < SS * WW; i += SS) {
        int w = i & (WW - 1);
        float phi = 0.1f * disp[w];
        float d = 0.95f * ww[i];
        d_tbl[i] = make_float2(d * cosf(phi), d * sinf(phi));
    }
}

// ---------------------------------------------------------------------------
// One integration step, fully fused:
//   coupled = conn @ field  (sparse, gathered from SMEM column panel)
//   f = g*(field+coupled)+b ; f /= (1+|f|^2/2) ; f *= phase*decay
// CTA = (batch b, wavelength w, half of m). Panel: all 256 rows x 32 cols.
// ---------------------------------------------------------------------------
template <bool PLANAR_IN, bool PLANAR_OUT>
__global__ __launch_bounds__(256) void step_kernel(
    const float* __restrict__ inR,   // planar: real plane;  interleaved: float2 base
    const float* __restrict__ inI,   // planar: imag plane;  interleaved: unused
    float* __restrict__ out,         // planar: base of (2,B,S,W,M); interleaved: float2 base
    const float* __restrict__ gain,
    const float* __restrict__ bias) {
    extern __shared__ float2 xs[];   // [SS * TC]

    int bid = blockIdx.x;
    int b = bid >> 7;                // 128 tiles per batch (64 w * 2 halves)
    int rem = bid & 127;
    int w = rem >> 1;
    int m0 = (rem & 1) * TC;
    int t = threadIdx.x;

    // element index of (b, s=0, w, m0)
    size_t base = (size_t)b * SS * WM + (size_t)w * MM + m0;

    // ---- stage column panel into SMEM ----
    if (PLANAR_IN) {
        for (int idx = t; idx < SS * TC; idx += 256) {
            int j = idx >> 5, mloc = idx & 31;
            size_t g = base + (size_t)j * WM + mloc;
            xs[(j << 5) + mloc] = make_float2(inR[g], inI[g]);
        }
    } else {
        const float4* src = (const float4*)inR;
        float4* dst = (float4*)xs;
        for (int idx = t; idx < SS * TC / 2; idx += 256) {
            int j = idx >> 4, q = idx & 15;
            // float2 element offset -> float4 offset = elem/2 (rows 32-elem aligned)
            dst[(j << 4) + q] = src[((base + (size_t)j * WM) >> 1) + q];
        }
    }
    __syncthreads();

    int warp = t >> 5, lane = t & 31;

    #pragma unroll 1
    for (int r = 0; r < 32; r++) {
        int row = (warp << 5) + r;
        int ks = d_row_ptr[row];
        int ke = d_row_ptr[row + 1];

        float ax = 0.f, ay = 0.f, cx = 0.f, cy = 0.f;
        int k = ks;
        for (; k + 2 <= ke; k += 2) {
            unsigned long long p0 = d_csr[k];
            unsigned long long p1 = d_csr[k + 1];
            int j0 = (int)(unsigned)p0;
            int j1 = (int)(unsigned)p1;
            float w0 = __uint_as_float((unsigned)(p0 >> 32));
            float w1 = __uint_as_float((unsigned)(p1 >> 32));
            float2 x0 = xs[(j0 << 5) + lane];
            float2 x1 = xs[(j1 << 5) + lane];
            ax = fmaf(w0, x0.x, ax);
            ay = fmaf(w0, x0.y, ay);
            cx = fmaf(w1, x1.x, cx);
            cy = fmaf(w1, x1.y, cy);
        }
        if (k < ke) {
            unsigned long long p0 = d_csr[k];
            int j0 = (int)(unsigned)p0;
            float w0 = __uint_as_float((unsigned)(p0 >> 32));
            float2 x0 = xs[(j0 << 5) + lane];
            ax = fmaf(w0, x0.x, ax);
            ay = fmaf(w0, x0.y, ay);
        }
        ax += cx;
        ay += cy;

        // ---- fused epilogue ----
        float2 old = xs[(row << 5) + lane];
        float gv = __ldg(&gain[row]);
        float bv = __ldg(&bias[row]);
        float fre = fmaf(gv, old.x + ax, bv);   // bias adds to real part only
        float fim = gv * (old.y + ay);
        float inten = fmaf(fre, fre, fim * fim);
        float sc = __frcp_rn(fmaf(0.5f, inten, 1.0f));
        fre *= sc;
        fim *= sc;
        float2 dcs = d_tbl[(row << 6) + w];
        float ore = fmaf(dcs.x, fre, -dcs.y * fim);
        float oim = fmaf(dcs.y, fre,  dcs.x * fim);

        size_t o = base + (size_t)row * WM + lane;
        if (PLANAR_OUT) {
            out[o] = ore;
            out[(size_t)ELEMS + o] = oim;
        } else {
            ((float2*)out)[o] = make_float2(ore, oim);
        }
    }
}

// ---------------------------------------------------------------------------
// kernel_launch: prep + 4 fused steps. Ping-pong: d_in -> scratch -> d_out
// (interleaved) -> scratch -> d_out (planar, final layout).
// ---------------------------------------------------------------------------
extern "C" void kernel_launch(void* const* d_in, const int* in_sizes, int n_in,
                              void* d_out, int out_size) {
    const float* fr   = (const float*)d_in[0];
    const float* fi   = (const float*)d_in[1];
    const float* conn = (const float*)d_in[2];
    const float* gain = (const float*)d_in[3];
    const float* bias = (const float*)d_in[4];
    const float* ww   = (const float*)d_in[5];
    const float* disp = (const float*)d_in[6];
    float* out = (float*)d_out;

    const size_t smem = (size_t)SS * TC * sizeof(float2);  // 64 KB
    cudaFuncSetAttribute(step_kernel<true,  false>,
                         cudaFuncAttributeMaxDynamicSharedMemorySize, (int)smem);
    cudaFuncSetAttribute(step_kernel<false, false>,
                         cudaFuncAttributeMaxDynamicSharedMemorySize, (int)smem);
    cudaFuncSetAttribute(step_kernel<false, true>,
                         cudaFuncAttributeMaxDynamicSharedMemorySize, (int)smem);

    float* scratch = nullptr;
    cudaGetSymbolAddress((void**)&scratch, d_scratch);

    prep_kernel<<<1, 256>>>(conn, ww, disp);

    dim3 grid(BB * WW * 2);  // 4096 CTAs
    // step 1: planar inputs -> interleaved scratch
    step_kernel<true,  false><<<grid, 256, smem>>>(fr, fi, scratch, gain, bias);
    // step 2: scratch -> d_out (interleaved, used as scratch)
    step_kernel<false, false><<<grid, 256, smem>>>(scratch, nullptr, out, gain, bias);
    // step 3: d_out -> scratch
    step_kernel<false, false><<<grid, 256, smem>>>(out, nullptr, scratch, gain, bias);
    // step 4: scratch -> d_out, final planar layout
    step_kernel<false, true><<<grid, 256, smem>>>(scratch, nullptr, out, gain, bias);
}

// round 4
// speedup vs baseline: 1.2258x; 1.2258x over previous
#include <cuda_runtime.h>
#include <cstdint>

// Problem constants (fixed shapes from reference)
#define SS 256        // S
#define WW 64         // W
#define MM 64         // M
#define BB 32         // B
#define WM 4096       // W*M
#define ELEMS 33554432  // B*S*W*M
#define TC 32         // columns (m) per CTA tile
#define NTHR 512      // threads per CTA
#define ROWS_PER_WARP 16

// Device-global scratch (allowed; no runtime allocation)
__device__ int d_row_ptr[SS + 1];
// padded CSR: entries packed (weight<<32 | j); each row padded to multiple of 4
__device__ __align__(16) unsigned long long d_csr[SS * (SS + 4)];
__device__ float2 d_tbl[SS * WW];      // (decay*cos, decay*sin) per (s,w)
__device__ float2 d_scratch[ELEMS];    // 268MB interleaved field buffer

// ---------------------------------------------------------------------------
// Prep: build padded CSR of W' = diag(gain) * (I + conn), plus fused
// phase/decay table. 1 CTA, 256 threads. Runs every launch (~microseconds).
// ---------------------------------------------------------------------------
__global__ void prep_kernel(const float* __restrict__ conn,
                            const float* __restrict__ gain,
                            const float* __restrict__ ww,
                            const float* __restrict__ disp) {
    __shared__ int cnt[SS + 1];
    int t = threadIdx.x;
    float g = gain[t];

    // count nonzeros of row t of (I + conn), pad to multiple of 4
    int c = 0;
    for (int j = 0; j < SS; j++) {
        float v = conn[t * SS + j] + (j == t ? 1.0f : 0.0f);
        if (v != 0.0f) c++;
    }
    cnt[t + 1] = (c + 3) & ~3;
    if (t == 0) cnt[0] = 0;
    __syncthreads();
    if (t == 0) {
        for (int i = 1; i <= SS; i++) cnt[i] += cnt[i - 1];
    }
    __syncthreads();

    int p = cnt[t];
    int pend = cnt[t + 1];
    for (int j = 0; j < SS; j++) {
        float v = conn[t * SS + j] + (j == t ? 1.0f : 0.0f);
        if (v != 0.0f) {
            d_csr[p++] = ((unsigned long long)__float_as_uint(g * v) << 32) | (unsigned)j;
        }
    }
    // zero-weight padding entries (gather row 0, weight 0.0 -> harmless)
    while (p < pend) d_csr[p++] = 0ull;

    d_row_ptr[t] = cnt[t];
    if (t == SS - 1) d_row_ptr[SS] = cnt[SS];

    // fused phase * decay table: phase = exp(i*0.1*disp[w]), decay = 0.95*ww[s][w]
    for (int i = t; i < SS * WW; i += SS) {
        int w = i & (WW - 1);
        float phi = 0.1f * disp[w];
        float d = 0.95f * ww[i];
        d_tbl[i] = make_float2(d * cosf(phi), d * sinf(phi));
    }
}

// ---------------------------------------------------------------------------
// One integration step, fully fused:
//   f_pre = W' @ field + bias           (sparse, gathered from SMEM panel;
//                                        W' = diag(g)(I+conn) so self-term is in)
//   f = f_pre / (1+|f_pre|^2/2) ; f *= phase*decay
// CTA = (batch b, wavelength w, half of m). Panel: all 256 rows x 32 cols.
// ---------------------------------------------------------------------------
template <bool PLANAR_IN, bool PLANAR_OUT>
__global__ __launch_bounds__(NTHR, 3) void step_kernel(
    const float* __restrict__ inR,   // planar: real plane;  interleaved: float2 base
    const float* __restrict__ inI,   // planar: imag plane;  interleaved: unused
    float* __restrict__ out,         // planar: base of (2,B,S,W,M); interleaved: float2 base
    const float* __restrict__ bias) {
    extern __shared__ float2 xs[];   // [SS * TC] = 64KB

    int bid = blockIdx.x;
    int b = bid >> 7;                // 128 tiles per batch (64 w * 2 halves)
    int rem = bid & 127;
    int w = rem >> 1;
    int m0 = (rem & 1) * TC;
    int t = threadIdx.x;

    // element index of (b, s=0, w, m0)
    size_t base = (size_t)b * SS * WM + (size_t)w * MM + m0;

    // ---- stage column panel into SMEM ----
    if (PLANAR_IN) {
        for (int idx = t; idx < SS * TC; idx += NTHR) {
            int j = idx >> 5, mloc = idx & 31;
            size_t gi = base + (size_t)j * WM + mloc;
            xs[(j << 5) + mloc] = make_float2(inR[gi], inI[gi]);
        }
    } else {
        const float4* src = (const float4*)inR;
        float4* dst = (float4*)xs;
        for (int idx = t; idx < SS * TC / 2; idx += NTHR) {
            int j = idx >> 4, q = idx & 15;
            dst[(j << 4) + q] = src[((base + (size_t)j * WM) >> 1) + q];
        }
    }
    __syncthreads();

    int warp = t >> 5, lane = t & 31;
    const ulonglong2* __restrict__ csr2 = (const ulonglong2*)d_csr;

    #pragma unroll 1
    for (int r = 0; r < ROWS_PER_WARP; r++) {
        int row = warp * ROWS_PER_WARP + r;
        int ks = d_row_ptr[row] >> 1;       // pair index (rows padded to 4 entries)
        int ke = d_row_ptr[row + 1] >> 1;

        float ax = 0.f, ay = 0.f, cx = 0.f, cy = 0.f;
        #pragma unroll 1
        for (int k = ks; k < ke; k += 2) {
            ulonglong2 q0 = csr2[k];        // entries 0,1 (LDG.128, uniform)
            ulonglong2 q1 = csr2[k + 1];    // entries 2,3
            int   j0 = (int)(unsigned)q0.x;
            int   j1 = (int)(unsigned)q0.y;
            int   j2 = (int)(unsigned)q1.x;
            int   j3 = (int)(unsigned)q1.y;
            float w0 = __uint_as_float((unsigned)(q0.x >> 32));
            float w1 = __uint_as_float((unsigned)(q0.y >> 32));
            float w2 = __uint_as_float((unsigned)(q1.x >> 32));
            float w3 = __uint_as_float((unsigned)(q1.y >> 32));
            float2 x0 = xs[(j0 << 5) + lane];
            float2 x1 = xs[(j1 << 5) + lane];
            float2 x2 = xs[(j2 << 5) + lane];
            float2 x3 = xs[(j3 << 5) + lane];
            ax = fmaf(w0, x0.x, ax);  ay = fmaf(w0, x0.y, ay);
            cx = fmaf(w1, x1.x, cx);  cy = fmaf(w1, x1.y, cy);
            ax = fmaf(w2, x2.x, ax);  ay = fmaf(w2, x2.y, ay);
            cx = fmaf(w3, x3.x, cx);  cy = fmaf(w3, x3.y, cy);
        }
        float fre = (ax + cx) + __ldg(&bias[row]);   // bias adds to real only
        float fim = (ay + cy);

        // ---- fused epilogue: saturation + rotation*decay ----
        float inten = fmaf(fre, fre, fim * fim);
        float sc = __frcp_rn(fmaf(0.5f, inten, 1.0f));
        fre *= sc;
        fim *= sc;
        float2 dcs = d_tbl[(row << 6) + w];
        float ore = fmaf(dcs.x, fre, -dcs.y * fim);
        float oim = fmaf(dcs.y, fre,  dcs.x * fim);

        size_t o = base + (size_t)row * WM + lane;
        if (PLANAR_OUT) {
            out[o] = ore;
            out[(size_t)ELEMS + o] = oim;
        } else {
            ((float2*)out)[o] = make_float2(ore, oim);
        }
    }
}

// ---------------------------------------------------------------------------
// kernel_launch: prep + 4 fused steps. Ping-pong: d_in -> scratch -> d_out
// (interleaved) -> scratch -> d_out (planar, final layout).
// ---------------------------------------------------------------------------
extern "C" void kernel_launch(void* const* d_in, const int* in_sizes, int n_in,
                              void* d_out, int out_size) {
    const float* fr   = (const float*)d_in[0];
    const float* fi   = (const float*)d_in[1];
    const float* conn = (const float*)d_in[2];
    const float* gain = (const float*)d_in[3];
    const float* bias = (const float*)d_in[4];
    const float* ww   = (const float*)d_in[5];
    const float* disp = (const float*)d_in[6];
    float* out = (float*)d_out;

    const size_t smem = (size_t)SS * TC * sizeof(float2);  // 64 KB
    cudaFuncSetAttribute(step_kernel<true,  false>,
                         cudaFuncAttributeMaxDynamicSharedMemorySize, (int)smem);
    cudaFuncSetAttribute(step_kernel<false, false>,
                         cudaFuncAttributeMaxDynamicSharedMemorySize, (int)smem);
    cudaFuncSetAttribute(step_kernel<false, true>,
                         cudaFuncAttributeMaxDynamicSharedMemorySize, (int)smem);

    float* scratch = nullptr;
    cudaGetSymbolAddress((void**)&scratch, d_scratch);

    prep_kernel<<<1, 256>>>(conn, gain, ww, disp);

    dim3 grid(BB * WW * 2);  // 4096 CTAs
    // step 1: planar inputs -> interleaved scratch
    step_kernel<true,  false><<<grid, NTHR, smem>>>(fr, fi, scratch, bias);
    // step 2: scratch -> d_out (interleaved, used as scratch)
    step_kernel<false, false><<<grid, NTHR, smem>>>(scratch, nullptr, out, bias);
    // step 3: d_out -> scratch
    step_kernel<false, false><<<grid, NTHR, smem>>>(out, nullptr, scratch, bias);
    // step 4: scratch -> d_out, final planar layout
    step_kernel<false, true><<<grid, NTHR, smem>>>(scratch, nullptr, out, bias);
}

// round 6
// speedup vs baseline: 1.5724x; 1.2828x over previous
#include <cuda_runtime.h>
#include <cuda_fp16.h>
#include <cstdint>

// Problem constants (fixed shapes from reference)
#define SS 256        // S
#define WW 64         // W
#define MM 64         // M
#define BB 32         // B
#define WM 4096       // W*M
#define ELEMS 33554432  // B*S*W*M
#define TC 32         // columns (m) per CTA tile
#define NTHR 512      // threads per CTA
#define ROWS_PER_WARP 16

// bit-cast helper (no __half2_as_uint intrinsic exists)
static __device__ __forceinline__ unsigned h2u(__half2 h) {
    return ((unsigned)__half_as_ushort(__high2half(h)) << 16) |
           (unsigned)__half_as_ushort(__low2half(h));
}

// Device-global scratch (allowed; no runtime allocation)
__device__ int d_row_ptr[SS + 1];
// padded CSR (diagonal EXCLUDED; weights pre-multiplied by gain):
// entries packed (weight<<32 | j); each row padded to multiple of 4; slack at end
__device__ __align__(16) unsigned long long d_csr[SS * (SS + 4) + 16];
__device__ float2 d_tbl[SS * WW];      // (decay*cos, decay*sin) per (s,w)
__device__ float2 d_scratch[ELEMS];    // 268MB interleaved field buffer

// ---------------------------------------------------------------------------
// Prep: padded CSR of diag(gain)*conn (no identity), fused phase/decay table.
// ---------------------------------------------------------------------------
__global__ void prep_kernel(const float* __restrict__ conn,
                            const float* __restrict__ gain,
                            const float* __restrict__ ww,
                            const float* __restrict__ disp) {
    __shared__ int cnt[SS + 1];
    int t = threadIdx.x;
    float g = gain[t];

    int c = 0;
    for (int j = 0; j < SS; j++)
        if (conn[t * SS + j] != 0.0f) c++;
    cnt[t + 1] = (c + 3) & ~3;           // pad rows to multiple of 4 entries
    if (t == 0) cnt[0] = 0;
    __syncthreads();
    if (t == 0) {
        for (int i = 1; i <= SS; i++) cnt[i] += cnt[i - 1];
    }
    __syncthreads();

    int p = cnt[t];
    int pend = cnt[t + 1];
    for (int j = 0; j < SS; j++) {
        float v = conn[t * SS + j];
        if (v != 0.0f)
            d_csr[p++] = ((unsigned long long)__float_as_uint(g * v) << 32) | (unsigned)j;
    }
    while (p < pend) d_csr[p++] = 0ull;  // zero-weight padding (gathers row 0)

    d_row_ptr[t] = cnt[t];
    if (t == SS - 1) {
        d_row_ptr[SS] = cnt[SS];
        // slack so unconditional quad loads past the end stay in-bounds
        for (int q = 0; q < 16; q++) d_csr[cnt[SS] + q] = 0ull;
    }

    // fused phase * decay: phase = exp(i*0.1*disp[w]), decay = 0.95*ww[s][w]
    for (int i = t; i < SS * WW; i += SS) {
        int w = i & (WW - 1);
        float phi = 0.1f * disp[w];
        float d = 0.95f * ww[i];
        d_tbl[i] = make_float2(d * cosf(phi), d * sinf(phi));
    }
}

// ---------------------------------------------------------------------------
// One fused step. Gather panel in SMEM as half2(re,im) -> LDS.32 per entry.
// Self term read exact (fp32) from gmem. Epilogue: gain/bias, saturation,
// rotation*decay fused.
// ---------------------------------------------------------------------------
template <bool PLANAR_IN, bool PLANAR_OUT>
__global__ __launch_bounds__(NTHR, 4) void step_kernel(
    const float* __restrict__ inR,   // planar: real plane;  interleaved: float2 base
    const float* __restrict__ inI,   // planar: imag plane;  interleaved: unused
    float* __restrict__ out,         // planar: (2,B,S,W,M); interleaved: float2 base
    const float* __restrict__ gain,
    const float* __restrict__ bias) {
    extern __shared__ __half2 xs[];  // [SS * TC] = 32KB

    int bid = blockIdx.x;
    int b = bid >> 7;                // 128 tiles per batch (64 w * 2 halves)
    int rem = bid & 127;
    int w = rem >> 1;
    int m0 = (rem & 1) * TC;
    int t = threadIdx.x;

    size_t base = (size_t)b * SS * WM + (size_t)w * MM + m0;  // (b, s=0, w, m0)

    // ---- stage panel into SMEM as half2 ----
    if (PLANAR_IN) {
        for (int idx = t; idx < SS * TC / 4; idx += NTHR) {   // 2048 float4-groups
            int j = idx >> 3, g4 = (idx & 7) << 2;
            size_t gi = base + (size_t)j * WM + g4;
            float4 re = *(const float4*)(inR + gi);
            float4 im = *(const float4*)(inI + gi);
            uint4 pk = make_uint4(h2u(__floats2half2_rn(re.x, im.x)),
                                  h2u(__floats2half2_rn(re.y, im.y)),
                                  h2u(__floats2half2_rn(re.z, im.z)),
                                  h2u(__floats2half2_rn(re.w, im.w)));
            *(uint4*)(xs + (j << 5) + g4) = pk;
        }
    } else {
        const float4* src = (const float4*)inR;
        for (int idx = t; idx < SS * TC / 2; idx += NTHR) {   // 4096 float4 (2 cplx)
            int j = idx >> 4, q = idx & 15;
            float4 v = src[((base + (size_t)j * WM) >> 1) + q];
            uint2 pk = make_uint2(h2u(__floats2half2_rn(v.x, v.y)),
                                  h2u(__floats2half2_rn(v.z, v.w)));
            *(uint2*)(xs + (j << 5) + (q << 1)) = pk;
        }
    }
    __syncthreads();

    int warp = t >> 5, lane = t & 31;
    const ulonglong2* __restrict__ csr2 = (const ulonglong2*)d_csr;

    #pragma unroll 1
    for (int r = 0; r < ROWS_PER_WARP; r++) {
        int row = warp * ROWS_PER_WARP + r;

        // exact fp32 self term, issued early (latency hidden by CSR loop)
        float sx, sy;
        {
            size_t gsel = base + (size_t)row * WM + lane;
            if (PLANAR_IN) {
                sx = __ldg(inR + gsel);
                sy = __ldg(inI + gsel);
            } else {
                float2 s = __ldg((const float2*)inR + gsel);
                sx = s.x; sy = s.y;
            }
        }

        int ks = d_row_ptr[row] >> 1;       // pair index; row len multiple of 4
        int ke = d_row_ptr[row + 1] >> 1;

        float ax = 0.f, ay = 0.f, cx = 0.f, cy = 0.f;
        #pragma unroll 2
        for (int k = ks; k < ke; k++) {
            ulonglong2 q0 = csr2[k];        // 2 entries (LDG.128, warp-uniform)
            int   j0 = (int)(unsigned)q0.x;
            int   j1 = (int)(unsigned)q0.y;
            float w0 = __uint_as_float((unsigned)(q0.x >> 32));
            float w1 = __uint_as_float((unsigned)(q0.y >> 32));
            float2 x0 = __half22float2(xs[(j0 << 5) + lane]);
            float2 x1 = __half22float2(xs[(j1 << 5) + lane]);
            ax = fmaf(w0, x0.x, ax);  ay = fmaf(w0, x0.y, ay);
            cx = fmaf(w1, x1.x, cx);  cy = fmaf(w1, x1.y, cy);
        }

        float gv = __ldg(&gain[row]);
        float bv = __ldg(&bias[row]);
        float fre = fmaf(gv, sx, fmaf(gv, ax + cx, bv));  // g*(self+coupled)+b (bias->real)
        float fim = fmaf(gv, sy, gv * (ay + cy));

        // saturation + rotation*decay
        float inten = fmaf(fre, fre, fim * fim);
        float sc = __frcp_rn(fmaf(0.5f, inten, 1.0f));
        fre *= sc;
        fim *= sc;
        float2 dcs = d_tbl[(row << 6) + w];
        float ore = fmaf(dcs.x, fre, -dcs.y * fim);
        float oim = fmaf(dcs.y, fre,  dcs.x * fim);

        size_t o = base + (size_t)row * WM + lane;
        if (PLANAR_OUT) {
            out[o] = ore;
            out[(size_t)ELEMS + o] = oim;
        } else {
            ((float2*)out)[o] = make_float2(ore, oim);
        }
    }
}

// ---------------------------------------------------------------------------
// kernel_launch: prep + 4 fused steps, ping-pong through scratch/d_out.
// ---------------------------------------------------------------------------
extern "C" void kernel_launch(void* const* d_in, const int* in_sizes, int n_in,
                              void* d_out, int out_size) {
    const float* fr   = (const float*)d_in[0];
    const float* fi   = (const float*)d_in[1];
    const float* conn = (const float*)d_in[2];
    const float* gain = (const float*)d_in[3];
    const float* bias = (const float*)d_in[4];
    const float* ww   = (const float*)d_in[5];
    const float* disp = (const float*)d_in[6];
    float* out = (float*)d_out;

    const size_t smem = (size_t)SS * TC * sizeof(__half2);  // 32 KB
    cudaFuncSetAttribute(step_kernel<true,  false>,
                         cudaFuncAttributeMaxDynamicSharedMemorySize, (int)smem);
    cudaFuncSetAttribute(step_kernel<false, false>,
                         cudaFuncAttributeMaxDynamicSharedMemorySize, (int)smem);
    cudaFuncSetAttribute(step_kernel<false, true>,
                         cudaFuncAttributeMaxDynamicSharedMemorySize, (int)smem);

    float* scratch = nullptr;
    cudaGetSymbolAddress((void**)&scratch, d_scratch);

    prep_kernel<<<1, 256>>>(conn, gain, ww, disp);

    dim3 grid(BB * WW * 2);  // 4096 CTAs
    // step 1: planar inputs -> interleaved scratch
    step_kernel<true,  false><<<grid, NTHR, smem>>>(fr, fi, scratch, gain, bias);
    // step 2: scratch -> d_out (interleaved, used as scratch)
    step_kernel<false, false><<<grid, NTHR, smem>>>(scratch, nullptr, out, gain, bias);
    // step 3: d_out -> scratch
    step_kernel<false, false><<<grid, NTHR, smem>>>(out, nullptr, scratch, gain, bias);
    // step 4: scratch -> d_out, final planar layout
    step_kernel<false, true><<<grid, NTHR, smem>>>(scratch, nullptr, out, gain, bias);
}

// round 7
// speedup vs baseline: 2.0948x; 1.3323x over previous
#include <cuda_runtime.h>
#include <cuda_fp16.h>
#include <cstdint>

// Problem constants (fixed shapes from reference)
#define SS 256        // S
#define WW 64         // W
#define MM 64         // M
#define BB 32         // B
#define WM 4096       // W*M
#define ELEMS 33554432  // B*S*W*M
#define TC 64         // columns (m) per CTA tile (full M per w)
#define NTHR 1024     // threads per CTA (32 warps)
#define ROWS_PER_WARP 8

// ---- packed helpers ----
static __device__ __forceinline__ unsigned h2u(__half2 h) {
    return ((unsigned)__half_as_ushort(__high2half(h)) << 16) |
           (unsigned)__half_as_ushort(__low2half(h));
}
static __device__ __forceinline__ unsigned long long pk2(float lo, float hi) {
    unsigned long long r;
    asm("mov.b64 %0, {%1, %2};" : "=l"(r) : "f"(lo), "f"(hi));
    return r;
}
static __device__ __forceinline__ void upk2(unsigned long long v, float& lo, float& hi) {
    asm("mov.b64 {%0, %1}, %2;" : "=f"(lo), "=f"(hi) : "l"(v));
}
#define FFMA2(acc, x, w) \
    asm("fma.rn.f32x2 %0, %1, %2, %0;" : "+l"(acc) : "l"(x), "l"(w))

// Device-global scratch (allowed; no runtime allocation)
__device__ int d_row_ptr[SS + 1];
// padded CSR (diag EXCLUDED; weights pre-multiplied by gain): (w<<32 | j),
// rows padded to multiple of 4 entries; slack at end
__device__ __align__(16) unsigned long long d_csr[SS * (SS + 4) + 16];
__device__ float2 d_tbl[SS * WW];      // (decay*cos, decay*sin) per (s,w)
__device__ float2 d_scratch[ELEMS];    // 268MB interleaved field buffer

// ---------------------------------------------------------------------------
// Prep: padded CSR of diag(gain)*conn, fused phase/decay table.
// ---------------------------------------------------------------------------
__global__ void prep_kernel(const float* __restrict__ conn,
                            const float* __restrict__ gain,
                            const float* __restrict__ ww,
                            const float* __restrict__ disp) {
    __shared__ int cnt[SS + 1];
    int t = threadIdx.x;
    float g = gain[t];

    int c = 0;
    for (int j = 0; j < SS; j++)
        if (conn[t * SS + j] != 0.0f) c++;
    cnt[t + 1] = (c + 3) & ~3;
    if (t == 0) cnt[0] = 0;
    __syncthreads();
    if (t == 0) {
        for (int i = 1; i <= SS; i++) cnt[i] += cnt[i - 1];
    }
    __syncthreads();

    int p = cnt[t];
    int pend = cnt[t + 1];
    for (int j = 0; j < SS; j++) {
        float v = conn[t * SS + j];
        if (v != 0.0f)
            d_csr[p++] = ((unsigned long long)__float_as_uint(g * v) << 32) | (unsigned)j;
    }
    while (p < pend) d_csr[p++] = 0ull;   // zero-weight padding (gathers row 0)

    d_row_ptr[t] = cnt[t];
    if (t == SS - 1) {
        d_row_ptr[SS] = cnt[SS];
        for (int q = 0; q < 16; q++) d_csr[cnt[SS] + q] = 0ull;
    }

    for (int i = t; i < SS * WW; i += SS) {
        int w = i & (WW - 1);
        float phi = 0.1f * disp[w];
        float d = 0.95f * ww[i];
        d_tbl[i] = make_float2(d * cosf(phi), d * sinf(phi));
    }
}

// ---------------------------------------------------------------------------
// One fused step. Panel: all 256 rows x 64 cols as half2(re,im) (64KB).
// Each thread owns 2 adjacent m-columns: gather = 1x LDS.64 per entry,
// accumulate with packed f32x2 FFMA. Self term exact fp32 from gmem.
// CSR weights already include gain; epilogue: +g*self+bias, saturate, rotate.
// ---------------------------------------------------------------------------
template <bool PLANAR_IN, bool PLANAR_OUT>
__global__ __launch_bounds__(NTHR, 2) void step_kernel(
    const float* __restrict__ inR,   // planar: real plane;  interleaved: float2 base
    const float* __restrict__ inI,   // planar: imag plane;  interleaved: unused
    float* __restrict__ out,         // planar: (2,B,S,W,M); interleaved: float2 base
    const float* __restrict__ gain,
    const float* __restrict__ bias) {
    extern __shared__ __half2 xs[];  // [SS * TC] = 64KB

    int bid = blockIdx.x;
    int b = bid >> 6;                // 64 w-tiles per batch
    int w = bid & 63;
    int t = threadIdx.x;

    size_t base = (size_t)b * SS * WM + (size_t)w * MM;   // (b, s=0, w, m=0)

    // ---- stage panel into SMEM as half2 ----
    if (PLANAR_IN) {
        for (int idx = t; idx < SS * TC / 4; idx += NTHR) {   // 4096 groups of 4 m
            int j = idx >> 4, g4 = (idx & 15) << 2;
            size_t gi = base + (size_t)j * WM + g4;
            float4 re = *(const float4*)(inR + gi);
            float4 im = *(const float4*)(inI + gi);
            uint4 pk = make_uint4(h2u(__floats2half2_rn(re.x, im.x)),
                                  h2u(__floats2half2_rn(re.y, im.y)),
                                  h2u(__floats2half2_rn(re.z, im.z)),
                                  h2u(__floats2half2_rn(re.w, im.w)));
            *(uint4*)(xs + (j << 6) + g4) = pk;
        }
    } else {
        const float4* src = (const float4*)inR;
        for (int idx = t; idx < SS * TC / 2; idx += NTHR) {   // 8192 float4 (2 cplx)
            int j = idx >> 5, q = idx & 31;
            float4 v = src[((base + (size_t)j * WM) >> 1) + q];
            uint2 pk = make_uint2(h2u(__floats2half2_rn(v.x, v.y)),
                                  h2u(__floats2half2_rn(v.z, v.w)));
            *(uint2*)(xs + (j << 6) + (q << 1)) = pk;
        }
    }
    __syncthreads();

    int warp = t >> 5, lane = t & 31;
    int lane2 = lane << 1;           // this thread's 2 m-columns
    const ulonglong2* __restrict__ csr2 = (const ulonglong2*)d_csr;

    #pragma unroll 1
    for (int r = 0; r < ROWS_PER_WARP; r++) {
        int row = warp * ROWS_PER_WARP + r;
        size_t o = base + (size_t)row * WM + lane2;   // complex-element index

        // exact fp32 self term for both columns (issued early)
        float sre0, sim0, sre1, sim1;
        if (PLANAR_IN) {
            float2 sr = *(const float2*)(inR + o);
            float2 si = *(const float2*)(inI + o);
            sre0 = sr.x; sre1 = sr.y; sim0 = si.x; sim1 = si.y;
        } else {
            float4 s = __ldg((const float4*)inR + (o >> 1));   // (re0,im0,re1,im1)
            sre0 = s.x; sim0 = s.y; sre1 = s.z; sim1 = s.w;
        }

        int ks = d_row_ptr[row] >> 1;       // pair index; row len multiple of 4
        int ke = d_row_ptr[row + 1] >> 1;

        // 4 packed accumulators: (re,im) per column per entry-parity chain
        unsigned long long aA0 = 0, aA1 = 0, aB0 = 0, aB1 = 0;
        #pragma unroll 2
        for (int k = ks; k < ke; k++) {
            ulonglong2 q = csr2[k];         // 2 entries (LDG.128, warp-uniform)
            int   j0 = (int)(unsigned)q.x;
            int   j1 = (int)(unsigned)q.y;
            float w0 = __uint_as_float((unsigned)(q.x >> 32));
            float w1 = __uint_as_float((unsigned)(q.y >> 32));
            uint2 x0 = *(const uint2*)(xs + (j0 << 6) + lane2);  // LDS.64
            uint2 x1 = *(const uint2*)(xs + (j1 << 6) + lane2);
            unsigned long long w0p = pk2(w0, w0);
            unsigned long long w1p = pk2(w1, w1);
            float2 f00 = __half22float2(*reinterpret_cast<const __half2*>(&x0.x));
            float2 f01 = __half22float2(*reinterpret_cast<const __half2*>(&x0.y));
            float2 f10 = __half22float2(*reinterpret_cast<const __half2*>(&x1.x));
            float2 f11 = __half22float2(*reinterpret_cast<const __half2*>(&x1.y));
            FFMA2(aA0, pk2(f00.x, f00.y), w0p);
            FFMA2(aA1, pk2(f01.x, f01.y), w0p);
            FFMA2(aB0, pk2(f10.x, f10.y), w1p);
            FFMA2(aB1, pk2(f11.x, f11.y), w1p);
        }

        float ar0, ai0, br0, bi0, ar1, ai1, br1, bi1;
        upk2(aA0, ar0, ai0); upk2(aB0, br0, bi0);
        upk2(aA1, ar1, ai1); upk2(aB1, br1, bi1);

        float gv = __ldg(&gain[row]);
        float bv = __ldg(&bias[row]);
        // coupled already carries gain (folded into CSR weights)
        float fre0 = fmaf(gv, sre0, (ar0 + br0) + bv);
        float fim0 = fmaf(gv, sim0, (ai0 + bi0));
        float fre1 = fmaf(gv, sre1, (ar1 + br1) + bv);
        float fim1 = fmaf(gv, sim1, (ai1 + bi1));

        // saturation + rotation*decay
        float2 dcs = d_tbl[(row << 6) + w];
        float it0 = fmaf(fre0, fre0, fim0 * fim0);
        float it1 = fmaf(fre1, fre1, fim1 * fim1);
        float sc0 = __frcp_rn(fmaf(0.5f, it0, 1.0f));
        float sc1 = __frcp_rn(fmaf(0.5f, it1, 1.0f));
        fre0 *= sc0; fim0 *= sc0;
        fre1 *= sc1; fim1 *= sc1;
        float ore0 = fmaf(dcs.x, fre0, -dcs.y * fim0);
        float oim0 = fmaf(dcs.y, fre0,  dcs.x * fim0);
        float ore1 = fmaf(dcs.x, fre1, -dcs.y * fim1);
        float oim1 = fmaf(dcs.y, fre1,  dcs.x * fim1);

        if (PLANAR_OUT) {
            *(float2*)(out + o) = make_float2(ore0, ore1);
            *(float2*)(out + (size_t)ELEMS + o) = make_float2(oim0, oim1);
        } else {
            *((float4*)out + (o >> 1)) = make_float4(ore0, oim0, ore1, oim1);
        }
    }
}

// ---------------------------------------------------------------------------
// kernel_launch: prep + 4 fused steps, ping-pong through scratch/d_out.
// ---------------------------------------------------------------------------
extern "C" void kernel_launch(void* const* d_in, const int* in_sizes, int n_in,
                              void* d_out, int out_size) {
    const float* fr   = (const float*)d_in[0];
    const float* fi   = (const float*)d_in[1];
    const float* conn = (const float*)d_in[2];
    const float* gain = (const float*)d_in[3];
    const float* bias = (const float*)d_in[4];
    const float* ww   = (const float*)d_in[5];
    const float* disp = (const float*)d_in[6];
    float* out = (float*)d_out;

    const size_t smem = (size_t)SS * TC * sizeof(__half2);  // 64 KB
    cudaFuncSetAttribute(step_kernel<true,  false>,
                         cudaFuncAttributeMaxDynamicSharedMemorySize, (int)smem);
    cudaFuncSetAttribute(step_kernel<false, false>,
                         cudaFuncAttributeMaxDynamicSharedMemorySize, (int)smem);
    cudaFuncSetAttribute(step_kernel<false, true>,
                         cudaFuncAttributeMaxDynamicSharedMemorySize, (int)smem);

    float* scratch = nullptr;
    cudaGetSymbolAddress((void**)&scratch, d_scratch);

    prep_kernel<<<1, 256>>>(conn, gain, ww, disp);

    dim3 grid(BB * WW);  // 2048 CTAs
    // step 1: planar inputs -> interleaved scratch
    step_kernel<true,  false><<<grid, NTHR, smem>>>(fr, fi, scratch, gain, bias);
    // step 2: scratch -> d_out (interleaved, used as scratch)
    step_kernel<false, false><<<grid, NTHR, smem>>>(scratch, nullptr, out, gain, bias);
    // step 3: d_out -> scratch
    step_kernel<false, false><<<grid, NTHR, smem>>>(out, nullptr, scratch, gain, bias);
    // step 4: scratch -> d_out, final planar layout
    step_kernel<false, true><<<grid, NTHR, smem>>>(scratch, nullptr, out, gain, bias);
}